// round 1
// baseline (speedup 1.0000x reference)
#include <cuda_runtime.h>

#define NN 512
#define BB 64
#define FF 128

// scratch (allocations forbidden -> device globals)
__device__ float g_sm[NN * NN];   // softmax(weight), 1 MB
__device__ float g_d[BB * NN];    // rsqrt degree, 128 KB

// ---------------------------------------------------------------------------
// Kernel 1: row softmax of weight [512,512]. One block per row, 256 threads.
// ---------------------------------------------------------------------------
__global__ __launch_bounds__(256) void softmax_kernel(const float* __restrict__ w) {
    int row = blockIdx.x;
    int t   = threadIdx.x;
    const float* wr = w + row * NN;
    float v0 = wr[t];
    float v1 = wr[t + 256];

    __shared__ float red[256];
    red[t] = fmaxf(v0, v1);
    __syncthreads();
#pragma unroll
    for (int s = 128; s > 0; s >>= 1) {
        if (t < s) red[t] = fmaxf(red[t], red[t + s]);
        __syncthreads();
    }
    float rmax = red[0];
    __syncthreads();

    float e0 = expf(v0 - rmax);
    float e1 = expf(v1 - rmax);
    red[t] = e0 + e1;
    __syncthreads();
#pragma unroll
    for (int s = 128; s > 0; s >>= 1) {
        if (t < s) red[t] += red[t + s];
        __syncthreads();
    }
    float inv = 1.0f / red[0];
    g_sm[row * NN + t]       = e0 * inv;
    g_sm[row * NN + t + 256] = e1 * inv;
}

// ---------------------------------------------------------------------------
// Kernel 2: d[b,i] = rsqrt(1 + sum_k sm[i,k]*mask[b,i,k]) with >0 guard.
// grid (512, 64), 128 threads: one block per (i,b) row; float4 loads.
// ---------------------------------------------------------------------------
__global__ __launch_bounds__(128) void degree_kernel(const float* __restrict__ mask) {
    int i = blockIdx.x;
    int b = blockIdx.y;
    int t = threadIdx.x;

    const float4* mr = (const float4*)(mask + ((size_t)b * NN + i) * NN);
    const float4* sr = (const float4*)(g_sm + (size_t)i * NN);
    float4 m4 = mr[t];
    float4 s4 = sr[t];
    float s = m4.x * s4.x + m4.y * s4.y + m4.z * s4.z + m4.w * s4.w;

#pragma unroll
    for (int o = 16; o > 0; o >>= 1) s += __shfl_xor_sync(0xffffffffu, s, o);

    __shared__ float ws[4];
    if ((t & 31) == 0) ws[t >> 5] = s;
    __syncthreads();
    if (t == 0) {
        float tot = ws[0] + ws[1] + ws[2] + ws[3] + 1.0f;  // +1 from identity
        g_d[b * NN + i] = (tot > 0.0f) ? rsqrtf(tot) : 0.0f;
    }
}

// ---------------------------------------------------------------------------
// Kernel 3: fused GEMM.
// out[b,i,f] = d_i * sum_k (sm[i,k]*mask[b,i,k]) * (d_k * x[b,k,f]) + d_i^2 * x[b,i,f]
// Tile: TM=64 (i) x TF=128 (f) x TK=32 (k). 256 threads, 4x8 microtile/thread.
// Accumulation via packed fma.rn.f32x2 (full-rate fp32 on sm_103a).
// ---------------------------------------------------------------------------
#define TM 64
#define TK 32
#define ASTRIDE 36   // TM-tile A is stored [i][k], stride TK+4 (bank-spread)

__device__ __forceinline__ unsigned long long pack2(float lo, float hi) {
    unsigned long long r;
    asm("mov.b64 %0, {%1, %2};" : "=l"(r) : "f"(lo), "f"(hi));
    return r;
}
__device__ __forceinline__ unsigned long long pack_dup(float a) {
    unsigned long long r;
    asm("mov.b64 %0, {%1, %1};" : "=l"(r) : "f"(a));
    return r;
}
__device__ __forceinline__ void fma2(unsigned long long& acc,
                                     unsigned long long a,
                                     unsigned long long b) {
    asm("fma.rn.f32x2 %0, %1, %2, %0;" : "+l"(acc) : "l"(a), "l"(b));
}

__global__ __launch_bounds__(256) void gcn_gemm_kernel(
    const float* __restrict__ x,     // [B,N,F]
    const float* __restrict__ mask,  // [B,N,N]
    float* __restrict__ out)         // [B,N,F]
{
    int b  = blockIdx.y;
    int i0 = blockIdx.x * TM;
    int t  = threadIdx.x;

    __shared__ float As[TM * ASTRIDE];  // A[i][k] = sm*mask
    __shared__ float Bs[TK * FF];       // B[k][f] = d_k * x[k][f]

    // microtile: 4 rows (i) x 8 cols (f) per thread; 16x16 thread grid
    const int tf = (t & 15) * 8;        // f base
    const int ti = (t >> 4) * 4;        // local i base

    unsigned long long acc[4][4];       // 4 rows x 4 packed-f32x2 (8 f cols)
#pragma unroll
    for (int r = 0; r < 4; r++)
#pragma unroll
        for (int c = 0; c < 4; c++) acc[r][c] = 0ULL;

    const float* maskB = mask + (size_t)b * NN * NN;
    const float* xB    = x + (size_t)b * NN * FF;
    const float* dB    = g_d + b * NN;

    // gmem load lane mapping
    const int a_r = t >> 3;           // 0..31 (i within tile)
    const int a_c = (t & 7) * 4;      // 0..28 (k quad)
    const int b_f = (t & 31) * 4;     // 0..124 (f quad)
    const int b_k = t >> 5;           // 0..7  (k row)

    for (int kt = 0; kt < NN / TK; ++kt) {
        int k0 = kt * TK;

        // --- load A tile: (sm * mask), 64x32, two float4 per thread ---
#pragma unroll
        for (int p = 0; p < 2; p++) {
            int il = a_r + p * 32;
            int gi = i0 + il;
            float4 s4 = *(const float4*)(g_sm + (size_t)gi * NN + k0 + a_c);
            float4 m4 = *(const float4*)(maskB + (size_t)gi * NN + k0 + a_c);
            float2 lo = make_float2(s4.x * m4.x, s4.y * m4.y);
            float2 hi = make_float2(s4.z * m4.z, s4.w * m4.w);
            *(float2*)(As + il * ASTRIDE + a_c)     = lo;
            *(float2*)(As + il * ASTRIDE + a_c + 2) = hi;
        }

        // --- load B tile: d_k * x, 32x128, four float4 per thread ---
#pragma unroll
        for (int p = 0; p < 4; p++) {
            int k  = b_k + p * 8;
            float dk = dB[k0 + k];
            float4 v = *(const float4*)(xB + (size_t)(k0 + k) * FF + b_f);
            v.x *= dk; v.y *= dk; v.z *= dk; v.w *= dk;
            *(float4*)(Bs + k * FF + b_f) = v;
        }
        __syncthreads();

        // --- inner product over TK ---
#pragma unroll
        for (int kk = 0; kk < TK; kk++) {
            float4 b0 = *(const float4*)(Bs + kk * FF + tf);
            float4 b1 = *(const float4*)(Bs + kk * FF + tf + 4);
            unsigned long long bb0 = pack2(b0.x, b0.y);
            unsigned long long bb1 = pack2(b0.z, b0.w);
            unsigned long long bb2 = pack2(b1.x, b1.y);
            unsigned long long bb3 = pack2(b1.z, b1.w);
#pragma unroll
            for (int r = 0; r < 4; r++) {
                unsigned long long aa = pack_dup(As[(ti + r) * ASTRIDE + kk]);
                fma2(acc[r][0], aa, bb0);
                fma2(acc[r][1], aa, bb1);
                fma2(acc[r][2], aa, bb2);
                fma2(acc[r][3], aa, bb3);
            }
        }
        __syncthreads();
    }

    // --- epilogue: out = d_i * acc + d_i^2 * x[i,f] ---
#pragma unroll
    for (int r = 0; r < 4; r++) {
        int gi    = i0 + ti + r;
        float di  = dB[gi];
        float di2 = di * di;
        const float* xr = xB + (size_t)gi * FF;
        float* orow     = out + ((size_t)b * NN + gi) * FF;
#pragma unroll
        for (int c = 0; c < 4; c++) {
            float lo, hi;
            asm("mov.b64 {%0, %1}, %2;" : "=f"(lo), "=f"(hi) : "l"(acc[r][c]));
            int f = tf + c * 2;
            float2 o;
            o.x = di * lo + di2 * xr[f];
            o.y = di * hi + di2 * xr[f + 1];
            *(float2*)(orow + f) = o;
        }
    }
}

// ---------------------------------------------------------------------------
extern "C" void kernel_launch(void* const* d_in, const int* in_sizes, int n_in,
                              void* d_out, int out_size) {
    // identify inputs by element count (robust to ordering)
    const float* input  = nullptr;  // 64*512*128 = 4194304
    const float* mask   = nullptr;  // 64*512*512 = 16777216
    const float* weight = nullptr;  // 512*512    = 262144
    for (int i = 0; i < n_in; i++) {
        if (in_sizes[i] == BB * NN * FF)      input  = (const float*)d_in[i];
        else if (in_sizes[i] == BB * NN * NN) mask   = (const float*)d_in[i];
        else if (in_sizes[i] == NN * NN)      weight = (const float*)d_in[i];
    }
    float* out = (float*)d_out;

    softmax_kernel<<<NN, 256>>>(weight);
    degree_kernel<<<dim3(NN, BB), 128>>>(mask);
    gcn_gemm_kernel<<<dim3(NN / TM, BB), 256>>>(input, mask, out);
}

// round 2
// speedup vs baseline: 1.4819x; 1.4819x over previous
#include <cuda_runtime.h>

#define NN 512
#define BB 64
#define FF 128
#define TM 128
#define TK 32

// scratch (allocations forbidden -> device globals)
__device__ float g_smw[NN * NN];  // softmax(weight)
__device__ float g_d[BB * NN];    // rsqrt degree

// ---------------- packed f32x2 helpers ----------------
__device__ __forceinline__ unsigned long long pack2(float lo, float hi) {
    unsigned long long r;
    asm("mov.b64 %0, {%1, %2};" : "=l"(r) : "f"(lo), "f"(hi));
    return r;
}
__device__ __forceinline__ unsigned long long pack_dup(float a) {
    unsigned long long r;
    asm("mov.b64 %0, {%1, %1};" : "=l"(r) : "f"(a));
    return r;
}
__device__ __forceinline__ void fma2(unsigned long long& acc,
                                     unsigned long long a,
                                     unsigned long long b) {
    asm("fma.rn.f32x2 %0, %1, %2, %0;" : "+l"(acc) : "l"(a), "l"(b));
}
__device__ __forceinline__ void unpack2(unsigned long long v, float& lo, float& hi) {
    asm("mov.b64 {%0, %1}, %2;" : "=f"(lo), "=f"(hi) : "l"(v));
}

// ---------------------------------------------------------------------------
// Kernel 1: row softmax of weight [512,512]. Warp per row, 64 blocks x 256.
// ---------------------------------------------------------------------------
__global__ __launch_bounds__(256) void softmax_kernel(const float* __restrict__ w) {
    int warp = threadIdx.x >> 5;
    int lane = threadIdx.x & 31;
    int row  = blockIdx.x * 8 + warp;

    const float4* wr = (const float4*)(w + (size_t)row * NN);
    float4 v[4];
    float mx = -1e30f;
#pragma unroll
    for (int j = 0; j < 4; j++) {
        v[j] = wr[lane + 32 * j];
        mx = fmaxf(mx, fmaxf(fmaxf(v[j].x, v[j].y), fmaxf(v[j].z, v[j].w)));
    }
#pragma unroll
    for (int o = 16; o; o >>= 1) mx = fmaxf(mx, __shfl_xor_sync(0xffffffffu, mx, o));

    float s = 0.0f;
#pragma unroll
    for (int j = 0; j < 4; j++) {
        v[j].x = __expf(v[j].x - mx);
        v[j].y = __expf(v[j].y - mx);
        v[j].z = __expf(v[j].z - mx);
        v[j].w = __expf(v[j].w - mx);
        s += v[j].x + v[j].y + v[j].z + v[j].w;
    }
#pragma unroll
    for (int o = 16; o; o >>= 1) s += __shfl_xor_sync(0xffffffffu, s, o);
    float inv = 1.0f / s;

    float4* orow = (float4*)(g_smw + (size_t)row * NN);
#pragma unroll
    for (int j = 0; j < 4; j++) {
        v[j].x *= inv; v[j].y *= inv; v[j].z *= inv; v[j].w *= inv;
        orow[lane + 32 * j] = v[j];
    }
}

// ---------------------------------------------------------------------------
// Kernel 2: d[b,i] = rsqrt(1 + sum_k sm[i,k]*mask[b,i,k]) with >0 guard.
// ---------------------------------------------------------------------------
__global__ __launch_bounds__(128) void degree_kernel(const float* __restrict__ mask) {
    int i = blockIdx.x;
    int b = blockIdx.y;
    int t = threadIdx.x;

    const float4* mr = (const float4*)(mask + ((size_t)b * NN + i) * NN);
    const float4* sr = (const float4*)(g_smw + (size_t)i * NN);
    float4 m4 = mr[t];
    float4 s4 = sr[t];
    float s = m4.x * s4.x + m4.y * s4.y + m4.z * s4.z + m4.w * s4.w;

#pragma unroll
    for (int o = 16; o > 0; o >>= 1) s += __shfl_xor_sync(0xffffffffu, s, o);

    __shared__ float ws[4];
    if ((t & 31) == 0) ws[t >> 5] = s;
    __syncthreads();
    if (t == 0) {
        float tot = ws[0] + ws[1] + ws[2] + ws[3] + 1.0f;  // +1 from identity
        g_d[b * NN + i] = (tot > 0.0f) ? rsqrtf(tot) : 0.0f;
    }
}

// ---------------------------------------------------------------------------
// Kernel 3: fused GEMM.
// out[b,i,f] = d_i * sum_k (sm[i,k]*mask[b,i,k]) * (d_k * x[b,k,f]) + d_i^2 * x[b,i,f]
// TM=128(i) x TF=128(f, full) x TK=32(k). 256 threads, 8x8 microtile.
// f-columns per thread split as [tf,tf+4) and [tf+64,tf+68) -> conflict-free Bs.
// ---------------------------------------------------------------------------
__global__ __launch_bounds__(256, 2) void gcn_gemm_kernel(
    const float* __restrict__ x,     // [B,N,F]
    const float* __restrict__ mask,  // [B,N,N]
    float* __restrict__ out)         // [B,N,F]
{
    __shared__ float As[TK][TM];   // A[k][i] = sm*mask (transposed for fast reads)
    __shared__ float Bs[TK][FF];   // B[k][f] = d_k * x[k][f]

    const int b  = blockIdx.y;
    const int i0 = blockIdx.x * TM;
    const int t  = threadIdx.x;

    const float* maskB = mask + (size_t)b * NN * NN;
    const float* xB    = x + (size_t)b * NN * FF;
    const float* dB    = g_d + b * NN;

    const int tf = (t & 15) * 4;   // f groups: tf and tf+64
    const int ti = (t >> 4) * 8;   // i rows: ti..ti+7

    // A loader: 4 lanes per row (8 floats each), 2 passes over 128 rows
    const int a_i = t >> 2;        // 0..63 (+64 on pass 1)
    const int a_k = (t & 3) * 8;   // k base: loads k..k+7

    // B loader: row k = t>>5 (+8 steps), 4 floats at (t&31)*4
    const int b_f = (t & 31) * 4;
    const int b_k = t >> 5;

    unsigned long long acc[8][4];
#pragma unroll
    for (int r = 0; r < 8; r++)
#pragma unroll
        for (int c = 0; c < 4; c++) acc[r][c] = 0ULL;

    for (int kt = 0; kt < NN / TK; ++kt) {
        const int k0 = kt * TK;

        // ---- A tile: As[k][i] = sm[i][k0+k] * mask[b][i][k0+k]
#pragma unroll
        for (int p = 0; p < 2; p++) {
            int i = a_i + p * 64;
            const float* sp = g_smw + (size_t)(i0 + i) * NN + k0 + a_k;
            const float* mp = maskB + (size_t)(i0 + i) * NN + k0 + a_k;
            float4 s0 = *(const float4*)sp;
            float4 s1 = *(const float4*)(sp + 4);
            float4 m0 = *(const float4*)mp;
            float4 m1 = *(const float4*)(mp + 4);
            As[a_k + 0][i] = s0.x * m0.x;
            As[a_k + 1][i] = s0.y * m0.y;
            As[a_k + 2][i] = s0.z * m0.z;
            As[a_k + 3][i] = s0.w * m0.w;
            As[a_k + 4][i] = s1.x * m1.x;
            As[a_k + 5][i] = s1.y * m1.y;
            As[a_k + 6][i] = s1.z * m1.z;
            As[a_k + 7][i] = s1.w * m1.w;
        }

        // ---- B tile: Bs[k][f] = d[k0+k] * x[b][k0+k][f]
#pragma unroll
        for (int p = 0; p < 4; p++) {
            int k  = b_k + p * 8;
            float dk = dB[k0 + k];
            float4 v = *(const float4*)(xB + (size_t)(k0 + k) * FF + b_f);
            v.x *= dk; v.y *= dk; v.z *= dk; v.w *= dk;
            *(float4*)&Bs[k][b_f] = v;
        }
        __syncthreads();

        // ---- inner product over TK
#pragma unroll 8
        for (int kk = 0; kk < TK; kk++) {
            float4 a0 = *(const float4*)&As[kk][ti];
            float4 a1 = *(const float4*)&As[kk][ti + 4];
            float4 b0 = *(const float4*)&Bs[kk][tf];
            float4 b1 = *(const float4*)&Bs[kk][tf + 64];
            unsigned long long bb0 = pack2(b0.x, b0.y);
            unsigned long long bb1 = pack2(b0.z, b0.w);
            unsigned long long bb2 = pack2(b1.x, b1.y);
            unsigned long long bb3 = pack2(b1.z, b1.w);
            float ar[8] = {a0.x, a0.y, a0.z, a0.w, a1.x, a1.y, a1.z, a1.w};
#pragma unroll
            for (int r = 0; r < 8; r++) {
                unsigned long long aa = pack_dup(ar[r]);
                fma2(acc[r][0], aa, bb0);
                fma2(acc[r][1], aa, bb1);
                fma2(acc[r][2], aa, bb2);
                fma2(acc[r][3], aa, bb3);
            }
        }
        __syncthreads();
    }

    // ---- epilogue: out = d_i * acc + d_i^2 * x[i,f]
#pragma unroll
    for (int r = 0; r < 8; r++) {
        int gi    = i0 + ti + r;
        float di  = dB[gi];
        float di2 = di * di;
        const float* xr = xB + (size_t)gi * FF;
        float* orow     = out + ((size_t)b * NN + gi) * FF;
        float4 x0 = *(const float4*)(xr + tf);
        float4 x1 = *(const float4*)(xr + tf + 64);
        float4 o0, o1;
        float lo, hi;
        unpack2(acc[r][0], lo, hi); o0.x = di * lo + di2 * x0.x; o0.y = di * hi + di2 * x0.y;
        unpack2(acc[r][1], lo, hi); o0.z = di * lo + di2 * x0.z; o0.w = di * hi + di2 * x0.w;
        unpack2(acc[r][2], lo, hi); o1.x = di * lo + di2 * x1.x; o1.y = di * hi + di2 * x1.y;
        unpack2(acc[r][3], lo, hi); o1.z = di * lo + di2 * x1.z; o1.w = di * hi + di2 * x1.w;
        *(float4*)(orow + tf)      = o0;
        *(float4*)(orow + tf + 64) = o1;
    }
}

// ---------------------------------------------------------------------------
extern "C" void kernel_launch(void* const* d_in, const int* in_sizes, int n_in,
                              void* d_out, int out_size) {
    const float* input  = nullptr;  // 64*512*128
    const float* mask   = nullptr;  // 64*512*512
    const float* weight = nullptr;  // 512*512
    for (int i = 0; i < n_in; i++) {
        if (in_sizes[i] == BB * NN * FF)      input  = (const float*)d_in[i];
        else if (in_sizes[i] == BB * NN * NN) mask   = (const float*)d_in[i];
        else if (in_sizes[i] == NN * NN)      weight = (const float*)d_in[i];
    }
    float* out = (float*)d_out;

    softmax_kernel<<<64, 256>>>(weight);
    degree_kernel<<<dim3(NN, BB), 128>>>(mask);
    gcn_gemm_kernel<<<dim3(NN / TM, BB), 256>>>(input, mask, out);
}

// round 3
// speedup vs baseline: 1.8064x; 1.2190x over previous
#include <cuda_runtime.h>
#include <mma.h>

using namespace nvcuda;

#define NN 512
#define BB 64
#define FF 128

#define BM 128
#define BK 32
#define ALDM 40    // As row stride (pad 8)
#define BLDM 136   // Bs row stride (pad 8)
#define ELD  68    // epilogue buffer row stride

// scratch (allocations forbidden -> device globals)
__device__ float g_smw[NN * NN];  // softmax(weight)
__device__ float g_d[BB * NN];    // rsqrt degree

// ---------------------------------------------------------------------------
// Kernel 1: row softmax of weight [512,512]. Warp per row.
// ---------------------------------------------------------------------------
__global__ __launch_bounds__(256) void softmax_kernel(const float* __restrict__ w) {
    int warp = threadIdx.x >> 5;
    int lane = threadIdx.x & 31;
    int row  = blockIdx.x * 8 + warp;

    const float4* wr = (const float4*)(w + (size_t)row * NN);
    float4 v[4];
    float mx = -1e30f;
#pragma unroll
    for (int j = 0; j < 4; j++) {
        v[j] = wr[lane + 32 * j];
        mx = fmaxf(mx, fmaxf(fmaxf(v[j].x, v[j].y), fmaxf(v[j].z, v[j].w)));
    }
#pragma unroll
    for (int o = 16; o; o >>= 1) mx = fmaxf(mx, __shfl_xor_sync(0xffffffffu, mx, o));

    float s = 0.0f;
#pragma unroll
    for (int j = 0; j < 4; j++) {
        v[j].x = __expf(v[j].x - mx);
        v[j].y = __expf(v[j].y - mx);
        v[j].z = __expf(v[j].z - mx);
        v[j].w = __expf(v[j].w - mx);
        s += v[j].x + v[j].y + v[j].z + v[j].w;
    }
#pragma unroll
    for (int o = 16; o; o >>= 1) s += __shfl_xor_sync(0xffffffffu, s, o);
    float inv = 1.0f / s;

    float4* orow = (float4*)(g_smw + (size_t)row * NN);
#pragma unroll
    for (int j = 0; j < 4; j++) {
        v[j].x *= inv; v[j].y *= inv; v[j].z *= inv; v[j].w *= inv;
        orow[lane + 32 * j] = v[j];
    }
}

// ---------------------------------------------------------------------------
// Kernel 2: d[b,i] = rsqrt(1 + sum_k sm[i,k]*mask[b,i,k]) with >0 guard.
// ---------------------------------------------------------------------------
__global__ __launch_bounds__(128) void degree_kernel(const float* __restrict__ mask) {
    int i = blockIdx.x;
    int b = blockIdx.y;
    int t = threadIdx.x;

    const float4* mr = (const float4*)(mask + ((size_t)b * NN + i) * NN);
    const float4* sr = (const float4*)(g_smw + (size_t)i * NN);
    float4 m4 = mr[t];
    float4 s4 = sr[t];
    float s = m4.x * s4.x + m4.y * s4.y + m4.z * s4.z + m4.w * s4.w;

#pragma unroll
    for (int o = 16; o > 0; o >>= 1) s += __shfl_xor_sync(0xffffffffu, s, o);

    __shared__ float ws[4];
    if ((t & 31) == 0) ws[t >> 5] = s;
    __syncthreads();
    if (t == 0) {
        float tot = ws[0] + ws[1] + ws[2] + ws[3] + 1.0f;  // +1 from identity
        g_d[b * NN + i] = (tot > 0.0f) ? rsqrtf(tot) : 0.0f;
    }
}

// ---------------------------------------------------------------------------
// Kernel 3: tf32 tensor-core GEMM.
// out[b,i,f] = d_i * sum_k (sm[i,k]*mask[b,i,k]) * (d_k*x[b,k,f]) + d_i^2 * x[b,i,f]
// BM=128 x BN=128(F) x BK=32. 8 warps = 4(m) x 2(n); warp tile 32x64;
// wmma m16n16k8 tf32 fragments, fp32 accumulate, fp32 identity term in epilogue.
// ---------------------------------------------------------------------------
__global__ __launch_bounds__(256, 2) void gcn_gemm_wmma(
    const float* __restrict__ x,     // [B,N,F]
    const float* __restrict__ mask,  // [B,N,N]
    float* __restrict__ out)         // [B,N,F]
{
    __shared__ __align__(128) float smem[BM * ALDM + BK * BLDM];  // 37.9 KB
    float* As = smem;                // [BM][ALDM]  A[i][k] = sm*mask
    float* Bs = smem + BM * ALDM;    // [BK][BLDM]  B[k][f] = d_k * x

    const int b  = blockIdx.y;
    const int i0 = blockIdx.x * BM;
    const int t  = threadIdx.x;
    const int warp = t >> 5;
    const int wm = (warp & 3) * 32;   // warp m offset
    const int wn = (warp >> 2) * 64;  // warp n offset

    const float* maskB = mask + (size_t)b * NN * NN;
    const float* xB    = x + (size_t)b * NN * FF;
    const float* dB    = g_d + b * NN;

    // A loader: 4 lanes per row (8 floats each), 2 passes over 128 rows
    const int a_i = t >> 2;          // 0..63 (+64)
    const int a_k = (t & 3) * 8;
    // B loader: row k = t>>5 (+8 per pass), 4 floats at (t&31)*4
    const int b_f = (t & 31) * 4;
    const int b_k = t >> 5;

    wmma::fragment<wmma::accumulator, 16, 16, 8, float> acc[2][4];
#pragma unroll
    for (int im = 0; im < 2; im++)
#pragma unroll
        for (int jn = 0; jn < 4; jn++) wmma::fill_fragment(acc[im][jn], 0.0f);

    for (int kt = 0; kt < NN / BK; ++kt) {
        const int k0 = kt * BK;

        // ---- A tile: As[i][k] = sm[i0+i][k0+k] * mask[b][i0+i][k0+k]
#pragma unroll
        for (int p = 0; p < 2; p++) {
            int i = a_i + p * 64;
            const float* sp = g_smw + (size_t)(i0 + i) * NN + k0 + a_k;
            const float* mp = maskB + (size_t)(i0 + i) * NN + k0 + a_k;
            float4 s0 = *(const float4*)sp;
            float4 s1 = *(const float4*)(sp + 4);
            float4 m0 = *(const float4*)mp;
            float4 m1 = *(const float4*)(mp + 4);
            float4 r0 = make_float4(s0.x * m0.x, s0.y * m0.y, s0.z * m0.z, s0.w * m0.w);
            float4 r1 = make_float4(s1.x * m1.x, s1.y * m1.y, s1.z * m1.z, s1.w * m1.w);
            *(float4*)(As + i * ALDM + a_k)     = r0;
            *(float4*)(As + i * ALDM + a_k + 4) = r1;
        }

        // ---- B tile: Bs[k][f] = d[k0+k] * x[b][k0+k][f]
#pragma unroll
        for (int p = 0; p < 4; p++) {
            int k  = b_k + p * 8;
            float dk = dB[k0 + k];
            float4 v = *(const float4*)(xB + (size_t)(k0 + k) * FF + b_f);
            v.x *= dk; v.y *= dk; v.z *= dk; v.w *= dk;
            *(float4*)(Bs + k * BLDM + b_f) = v;
        }
        __syncthreads();

        // ---- tensor-core inner product: 4 k-steps of 8
#pragma unroll
        for (int kk = 0; kk < 4; kk++) {
            wmma::fragment<wmma::matrix_a, 16, 16, 8, wmma::precision::tf32, wmma::row_major> af[2];
            wmma::fragment<wmma::matrix_b, 16, 16, 8, wmma::precision::tf32, wmma::row_major> bf[4];
#pragma unroll
            for (int im = 0; im < 2; im++) {
                wmma::load_matrix_sync(af[im], As + (wm + im * 16) * ALDM + kk * 8, ALDM);
#pragma unroll
                for (int e = 0; e < af[im].num_elements; e++)
                    af[im].x[e] = wmma::__float_to_tf32(af[im].x[e]);
            }
#pragma unroll
            for (int jn = 0; jn < 4; jn++) {
                wmma::load_matrix_sync(bf[jn], Bs + (kk * 8) * BLDM + wn + jn * 16, BLDM);
#pragma unroll
                for (int e = 0; e < bf[jn].num_elements; e++)
                    bf[jn].x[e] = wmma::__float_to_tf32(bf[jn].x[e]);
            }
#pragma unroll
            for (int im = 0; im < 2; im++)
#pragma unroll
                for (int jn = 0; jn < 4; jn++)
                    wmma::mma_sync(acc[im][jn], af[im], bf[jn], acc[im][jn]);
        }
        __syncthreads();
    }

    // ---- epilogue: stage acc through smem (two n-halves), apply
    //      out = d_i * acc + d_i^2 * x[i,f] in fp32
    float* buf = smem;  // [BM][ELD], 34.8 KB, reuses As/Bs
    const int er = t >> 1;             // row 0..127
    const int ec = (t & 1) * 32;       // col half within 64
#pragma unroll
    for (int half = 0; half < 2; half++) {
        __syncthreads();
        if ((warp >> 2) == half) {
#pragma unroll
            for (int im = 0; im < 2; im++)
#pragma unroll
                for (int jn = 0; jn < 4; jn++)
                    wmma::store_matrix_sync(buf + (wm + im * 16) * ELD + jn * 16,
                                            acc[im][jn], ELD, wmma::mem_row_major);
        }
        __syncthreads();

        int gi = i0 + er;
        float di  = dB[gi];
        float di2 = di * di;
        const float* xr = xB + (size_t)gi * FF + half * 64 + ec;
        float* orow     = out + ((size_t)b * NN + gi) * FF + half * 64 + ec;
#pragma unroll
        for (int q = 0; q < 8; q++) {
            float4 v  = *(const float4*)(buf + er * ELD + ec + q * 4);
            float4 xv = *(const float4*)(xr + q * 4);
            float4 o;
            o.x = di * v.x + di2 * xv.x;
            o.y = di * v.y + di2 * xv.y;
            o.z = di * v.z + di2 * xv.z;
            o.w = di * v.w + di2 * xv.w;
            *(float4*)(orow + q * 4) = o;
        }
    }
}

// ---------------------------------------------------------------------------
extern "C" void kernel_launch(void* const* d_in, const int* in_sizes, int n_in,
                              void* d_out, int out_size) {
    const float* input  = nullptr;  // 64*512*128
    const float* mask   = nullptr;  // 64*512*512
    const float* weight = nullptr;  // 512*512
    for (int i = 0; i < n_in; i++) {
        if (in_sizes[i] == BB * NN * FF)      input  = (const float*)d_in[i];
        else if (in_sizes[i] == BB * NN * NN) mask   = (const float*)d_in[i];
        else if (in_sizes[i] == NN * NN)      weight = (const float*)d_in[i];
    }
    float* out = (float*)d_out;

    softmax_kernel<<<64, 256>>>(weight);
    degree_kernel<<<dim3(NN, BB), 128>>>(mask);
    gcn_gemm_wmma<<<dim3(NN / BM, BB), 256>>>(input, mask, out);
}

// round 6
// speedup vs baseline: 2.0259x; 1.1215x over previous
#include <cuda_runtime.h>
#include <mma.h>

using namespace nvcuda;

#define NN 512
#define BB 64
#define FF 128

#define BM 128
#define BK 32
#define ALDM 40    // As row stride (pad 8) — round-3 proven layout
#define BLDM 136   // Bs row stride
#define ELD  68    // epilogue buffer row stride

// scratch (allocations forbidden -> device globals)
__device__ float g_smw[NN * NN];  // softmax(weight)
__device__ float g_d[BB * NN];    // rsqrt degree

__device__ __forceinline__ float4 tf32x4(float a, float b, float c, float d) {
    return make_float4(wmma::__float_to_tf32(a), wmma::__float_to_tf32(b),
                       wmma::__float_to_tf32(c), wmma::__float_to_tf32(d));
}

// ---------------------------------------------------------------------------
// Kernel 1: row softmax of weight [512,512]. Warp per row.
// ---------------------------------------------------------------------------
__global__ __launch_bounds__(256) void softmax_kernel(const float* __restrict__ w) {
    int warp = threadIdx.x >> 5;
    int lane = threadIdx.x & 31;
    int row  = blockIdx.x * 8 + warp;

    const float4* wr = (const float4*)(w + (size_t)row * NN);
    float4 v[4];
    float mx = -1e30f;
#pragma unroll
    for (int j = 0; j < 4; j++) {
        v[j] = wr[lane + 32 * j];
        mx = fmaxf(mx, fmaxf(fmaxf(v[j].x, v[j].y), fmaxf(v[j].z, v[j].w)));
    }
#pragma unroll
    for (int o = 16; o; o >>= 1) mx = fmaxf(mx, __shfl_xor_sync(0xffffffffu, mx, o));

    float s = 0.0f;
#pragma unroll
    for (int j = 0; j < 4; j++) {
        v[j].x = __expf(v[j].x - mx);
        v[j].y = __expf(v[j].y - mx);
        v[j].z = __expf(v[j].z - mx);
        v[j].w = __expf(v[j].w - mx);
        s += v[j].x + v[j].y + v[j].z + v[j].w;
    }
#pragma unroll
    for (int o = 16; o; o >>= 1) s += __shfl_xor_sync(0xffffffffu, s, o);
    float inv = 1.0f / s;

    float4* orow = (float4*)(g_smw + (size_t)row * NN);
#pragma unroll
    for (int j = 0; j < 4; j++) {
        v[j].x *= inv; v[j].y *= inv; v[j].z *= inv; v[j].w *= inv;
        orow[lane + 32 * j] = v[j];
    }
}

// ---------------------------------------------------------------------------
// Kernel 2: d[b,i] = rsqrt(1 + sum_k sm[i,k]*mask[b,i,k]) with >0 guard.
// Warp per row, 8 rows per block. grid (64, 64) x 256.
// ---------------------------------------------------------------------------
__global__ __launch_bounds__(256) void degree_kernel(const float* __restrict__ mask) {
    int warp = threadIdx.x >> 5;
    int lane = threadIdx.x & 31;
    int i = blockIdx.x * 8 + warp;
    int b = blockIdx.y;

    const float4* mr = (const float4*)(mask + ((size_t)b * NN + i) * NN);
    const float4* sr = (const float4*)(g_smw + (size_t)i * NN);
    float s = 0.0f;
#pragma unroll
    for (int j = 0; j < 4; j++) {
        float4 m4 = mr[lane + 32 * j];
        float4 s4 = sr[lane + 32 * j];
        s += m4.x * s4.x + m4.y * s4.y + m4.z * s4.z + m4.w * s4.w;
    }
#pragma unroll
    for (int o = 16; o > 0; o >>= 1) s += __shfl_xor_sync(0xffffffffu, s, o);
    if (lane == 0) {
        float tot = s + 1.0f;  // +1 from identity
        g_d[b * NN + i] = (tot > 0.0f) ? rsqrtf(tot) : 0.0f;
    }
}

// ---------------------------------------------------------------------------
// Kernel 3: tf32 tensor-core GEMM — EXACT round-3 structure (passing),
// with the single change: tf32 RN conversion at smem staging instead of
// per-fragment-element (index mappings untouched).
// out[b,i,f] = d_i * sum_k (sm[i,k]*mask[b,i,k]) * (d_k*x[b,k,f]) + d_i^2 * x[b,i,f]
// ---------------------------------------------------------------------------
__global__ __launch_bounds__(256, 2) void gcn_gemm_wmma(
    const float* __restrict__ x,     // [B,N,F]
    const float* __restrict__ mask,  // [B,N,N]
    float* __restrict__ out)         // [B,N,F]
{
    __shared__ __align__(128) float smem[BM * ALDM + BK * BLDM];  // 37.9 KB
    float* As = smem;                // [BM][ALDM]  A[i][k] = tf32(sm*mask)
    float* Bs = smem + BM * ALDM;    // [BK][BLDM]  B[k][f] = tf32(d_k * x)

    const int b  = blockIdx.y;
    const int i0 = blockIdx.x * BM;
    const int t  = threadIdx.x;
    const int warp = t >> 5;
    const int wm = (warp & 3) * 32;   // warp m offset
    const int wn = (warp >> 2) * 64;  // warp n offset

    const float* maskB = mask + (size_t)b * NN * NN;
    const float* xB    = x + (size_t)b * NN * FF;
    const float* dB    = g_d + b * NN;

    // A loader: 4 lanes per row (8 floats each), 2 passes over 128 rows
    const int a_i = t >> 2;          // 0..63 (+64)
    const int a_k = (t & 3) * 8;
    // B loader: row k = t>>5 (+8 per pass), 4 floats at (t&31)*4
    const int b_f = (t & 31) * 4;
    const int b_k = t >> 5;

    wmma::fragment<wmma::accumulator, 16, 16, 8, float> acc[2][4];
#pragma unroll
    for (int im = 0; im < 2; im++)
#pragma unroll
        for (int jn = 0; jn < 4; jn++) wmma::fill_fragment(acc[im][jn], 0.0f);

    for (int kt = 0; kt < NN / BK; ++kt) {
        const int k0 = kt * BK;

        // ---- A tile: As[i][k] = tf32(sm[i0+i][k0+k] * mask[b][i0+i][k0+k])
#pragma unroll
        for (int p = 0; p < 2; p++) {
            int i = a_i + p * 64;
            const float* sp = g_smw + (size_t)(i0 + i) * NN + k0 + a_k;
            const float* mp = maskB + (size_t)(i0 + i) * NN + k0 + a_k;
            float4 s0 = *(const float4*)sp;
            float4 s1 = *(const float4*)(sp + 4);
            float4 m0 = *(const float4*)mp;
            float4 m1 = *(const float4*)(mp + 4);
            float4 r0 = tf32x4(s0.x * m0.x, s0.y * m0.y, s0.z * m0.z, s0.w * m0.w);
            float4 r1 = tf32x4(s1.x * m1.x, s1.y * m1.y, s1.z * m1.z, s1.w * m1.w);
            *(float4*)(As + i * ALDM + a_k)     = r0;
            *(float4*)(As + i * ALDM + a_k + 4) = r1;
        }

        // ---- B tile: Bs[k][f] = tf32(d[k0+k] * x[b][k0+k][f])
#pragma unroll
        for (int p = 0; p < 4; p++) {
            int k  = b_k + p * 8;
            float dk = dB[k0 + k];
            float4 v = *(const float4*)(xB + (size_t)(k0 + k) * FF + b_f);
            *(float4*)(Bs + k * BLDM + b_f) = tf32x4(v.x * dk, v.y * dk, v.z * dk, v.w * dk);
        }
        __syncthreads();

        // ---- tensor-core inner product: 4 k-steps of 8 (values pre-converted)
#pragma unroll
        for (int kk = 0; kk < 4; kk++) {
            wmma::fragment<wmma::matrix_a, 16, 16, 8, wmma::precision::tf32, wmma::row_major> af[2];
            wmma::fragment<wmma::matrix_b, 16, 16, 8, wmma::precision::tf32, wmma::row_major> bf[4];
#pragma unroll
            for (int im = 0; im < 2; im++)
                wmma::load_matrix_sync(af[im], As + (wm + im * 16) * ALDM + kk * 8, ALDM);
#pragma unroll
            for (int jn = 0; jn < 4; jn++)
                wmma::load_matrix_sync(bf[jn], Bs + (kk * 8) * BLDM + wn + jn * 16, BLDM);
#pragma unroll
            for (int im = 0; im < 2; im++)
#pragma unroll
                for (int jn = 0; jn < 4; jn++)
                    wmma::mma_sync(acc[im][jn], af[im], bf[jn], acc[im][jn]);
        }
        __syncthreads();
    }

    // ---- epilogue: stage acc through smem (two n-halves), apply
    //      out = d_i * acc + d_i^2 * x[i,f] in fp32
    float* buf = smem;  // [BM][ELD], reuses As/Bs
    const int er = t >> 1;             // row 0..127
    const int ec = (t & 1) * 32;       // col half within 64
#pragma unroll
    for (int half = 0; half < 2; half++) {
        __syncthreads();
        if ((warp >> 2) == half) {
#pragma unroll
            for (int im = 0; im < 2; im++)
#pragma unroll
                for (int jn = 0; jn < 4; jn++)
                    wmma::store_matrix_sync(buf + (wm + im * 16) * ELD + jn * 16,
                                            acc[im][jn], ELD, wmma::mem_row_major);
        }
        __syncthreads();

        int gi = i0 + er;
        float di  = dB[gi];
        float di2 = di * di;
        const float* xr = xB + (size_t)gi * FF + half * 64 + ec;
        float* orow     = out + ((size_t)b * NN + gi) * FF + half * 64 + ec;
#pragma unroll
        for (int q = 0; q < 8; q++) {
            float4 v  = *(const float4*)(buf + er * ELD + ec + q * 4);
            float4 xv = *(const float4*)(xr + q * 4);
            float4 o;
            o.x = di * v.x + di2 * xv.x;
            o.y = di * v.y + di2 * xv.y;
            o.z = di * v.z + di2 * xv.z;
            o.w = di * v.w + di2 * xv.w;
            *(float4*)(orow + q * 4) = o;
        }
    }
}

// ---------------------------------------------------------------------------
extern "C" void kernel_launch(void* const* d_in, const int* in_sizes, int n_in,
                              void* d_out, int out_size) {
    const float* input  = nullptr;  // 64*512*128
    const float* mask   = nullptr;  // 64*512*512
    const float* weight = nullptr;  // 512*512
    for (int i = 0; i < n_in; i++) {
        if (in_sizes[i] == BB * NN * FF)      input  = (const float*)d_in[i];
        else if (in_sizes[i] == BB * NN * NN) mask   = (const float*)d_in[i];
        else if (in_sizes[i] == NN * NN)      weight = (const float*)d_in[i];
    }
    float* out = (float*)d_out;

    softmax_kernel<<<64, 256>>>(weight);
    degree_kernel<<<dim3(64, BB), 256>>>(mask);
    gcn_gemm_wmma<<<dim3(NN / BM, BB), 256>>>(input, mask, out);
}